// round 4
// baseline (speedup 1.0000x reference)
#include <cuda_runtime.h>
#include <cstdint>

// ============================================================================
// DynamicConv1D: T=2048, B=16, C=512, H=8, R=64, K=7
//   phase 1: logits = query @ W  (32768 x 512) * (512 x 56), softmax over K=7
//   phase 2: out[t,b,h*64+r] = sum_kk w[n,h,kk] * xs[tl*512 + h*448 + r*7 + kk]
// ============================================================================

#define T_DIM 2048
#define B_DIM 16
#define C_DIM 512
#define H_DIM 8
#define K_DIM 7

// scratch: softmaxed weights, padded: [row(=t*16+b)] [8 heads] [8 slots]
__device__ float g_weights[(size_t)T_DIM * B_DIM * H_DIM * 8];

// ---------------------------------------------------------------------------
// Kernel 1: GEMM (M=32768, N=56, K=512) + fused softmax.
// 128 threads = 4 warps. Warp w covers heads {2w, 2w+1}: lane = (rg = lane&15,
// hsel = lane>>4), head = 2w + hsel. Each lane owns 8 rows: {4rg..4rg+3} and
// {64+4rg..64+4rg+3}, x 7 cols of its head -> 28 f32x2 accumulators.
// A tile K-major with pad 132 + XOR swizzle of row bits[2:3] by (kk>>2)&3:
//   store conflicts 2-way, loads contiguous LDS.128 (lane permutation rg^c).
// B tile lane-duplicated float2; reads are half-warp broadcasts (1 wf).
// ---------------------------------------------------------------------------
#define BM  128
#define BK  32
#define BMP 132

__device__ __forceinline__ unsigned long long fma2(unsigned long long a,
                                                   unsigned long long b,
                                                   unsigned long long c) {
    asm("fma.rn.f32x2 %0, %1, %2, %0;" : "+l"(c) : "l"(a), "l"(b));
    return c;
}

__global__ __launch_bounds__(128, 4)
void gemm_softmax_kernel(const float* __restrict__ query,
                         const float* __restrict__ W) {
    __shared__ float  As[BK * BMP];     // [kk][rowphys], 16896 B
    __shared__ float2 Bsd[BK * 64];     // [kk][head*8+j] duplicated, 16384 B

    const int tid      = threadIdx.x;
    const int wid      = tid >> 5;
    const int lane     = tid & 31;
    const int rg       = lane & 15;
    const int hsel     = lane >> 4;
    const int head     = wid * 2 + hsel;
    const int blockRow = blockIdx.x * BM;

    unsigned long long accP[4][7];
    #pragma unroll
    for (int p = 0; p < 4; p++)
        #pragma unroll
        for (int j = 0; j < 7; j++) accP[p][j] = 0ULL;

    for (int k0 = 0; k0 < C_DIM; k0 += BK) {
        // ---- load A tile (128 rows x 32 kk), store K-major swizzled ----
        #pragma unroll
        for (int l = 0; l < 8; l++) {
            int linear = tid + l * 128;        // 0..1023
            int row    = linear >> 3;          // 0..127
            int f4     = linear & 7;           // 0..7 (kk quad)
            float4 v = *(const float4*)(query + (size_t)(blockRow + row) * C_DIM + k0 + f4 * 4);
            int rp = row ^ (4 * (f4 & 3));     // swizzle bits[2:3] by c=(kk>>2)&3=f4&3
            As[(f4 * 4 + 0) * BMP + rp] = v.x;
            As[(f4 * 4 + 1) * BMP + rp] = v.y;
            As[(f4 * 4 + 2) * BMP + rp] = v.z;
            As[(f4 * 4 + 3) * BMP + rp] = v.w;
        }
        // ---- load B tile, lane-duplicated float2: 2048 elems, 16/thread ----
        #pragma unroll
        for (int l = 0; l < 16; l++) {
            int linear = tid + l * 128;        // 0..2047
            int kk   = linear >> 6;
            int slot = linear & 63;
            int hs   = slot >> 3;
            int jj   = slot & 7;
            float w = 0.0f;
            if (jj < 7) w = W[(k0 + kk) * 56 + hs * 7 + jj];
            Bsd[linear] = make_float2(w, w);
        }
        __syncthreads();

        for (int kc = 0; kc < 8; kc++) {
            const int rgx = 4 * (rg ^ (kc & 3));   // physical quad base for this c
            #pragma unroll
            for (int ku = 0; ku < 4; ku++) {
                const int kk = kc * 4 + ku;
                // A: rows {4rg..+3} and {64+4rg..+3}, contiguous after unswizzle
                ulonglong2 a0 = *(const ulonglong2*)&As[kk * BMP + rgx];
                ulonglong2 a1 = *(const ulonglong2*)&As[kk * BMP + 64 + rgx];
                // B: 7 duplicated pairs for this head (half-warp broadcast)
                const ulonglong2* bp = (const ulonglong2*)&Bsd[kk * 64 + head * 8];
                ulonglong2 b01 = bp[0], b23 = bp[1], b45 = bp[2], b67 = bp[3];
                unsigned long long b[7] = {b01.x, b01.y, b23.x, b23.y, b45.x, b45.y, b67.x};
                #pragma unroll
                for (int j = 0; j < 7; j++) {
                    accP[0][j] = fma2(a0.x, b[j], accP[0][j]);
                    accP[1][j] = fma2(a0.y, b[j], accP[1][j]);
                    accP[2][j] = fma2(a1.x, b[j], accP[2][j]);
                    accP[3][j] = fma2(a1.y, b[j], accP[3][j]);
                }
            }
        }
        __syncthreads();
    }

    // ---- unpack, softmax over the 7 taps, store padded to 8 ----
    #pragma unroll
    for (int p = 0; p < 4; p++) {
        float lo[7], hi[7];
        #pragma unroll
        for (int j = 0; j < 7; j++) {
            unsigned int ulo, uhi;
            asm("mov.b64 {%0, %1}, %2;" : "=r"(ulo), "=r"(uhi) : "l"(accP[p][j]));
            lo[j] = __uint_as_float(ulo);
            hi[j] = __uint_as_float(uhi);
        }
        int rbase2 = blockRow + ((p >> 1) ? 64 : 0) + 4 * rg + (p & 1) * 2;
        #pragma unroll
        for (int half = 0; half < 2; half++) {
            float* v = half ? hi : lo;
            int rowGlobal = rbase2 + half;
            float m = v[0];
            #pragma unroll
            for (int j = 1; j < 7; j++) m = fmaxf(m, v[j]);
            float e[7], s = 0.0f;
            #pragma unroll
            for (int j = 0; j < 7; j++) { e[j] = __expf(v[j] - m); s += e[j]; }
            float inv = 1.0f / s;
            size_t n8 = ((size_t)rowGlobal * 8 + head) * 8;
            *(float4*)&g_weights[n8]     = make_float4(e[0]*inv, e[1]*inv, e[2]*inv, e[3]*inv);
            *(float4*)&g_weights[n8 + 4] = make_float4(e[4]*inv, e[5]*inv, e[6]*inv, 0.0f);
        }
    }
}

// ---------------------------------------------------------------------------
// Kernel 2: gathered conv. Block = (t-tile of 16, one b). 512 threads, thread
// owns one channel c for all 16 t. x staged in smem [22 x 512] (halo 3+3),
// weights staged [16 x 64]. Taps are 7 consecutive smem floats (lane stride 7
// words -> conflict-free since gcd(7,32)=1). 48 KB smem + 32-reg cap ->
// 4 blocks/SM = 2048 threads = 100% occupancy.
// ---------------------------------------------------------------------------
#define TT 16
#define XS_ROWS (TT + K_DIM - 1)            // 22
#define SMEM_CONV ((XS_ROWS * C_DIM + TT * 64) * 4)   // 49152 bytes

__global__ __launch_bounds__(512, 4)
void conv_kernel(const float* __restrict__ x, float* __restrict__ out) {
    extern __shared__ float smem[];
    float* xs = smem;                        // 22*512
    float* ws = smem + XS_ROWS * C_DIM;      // 16*64

    const int tid = threadIdx.x;
    const int t0  = (blockIdx.x >> 4) * TT;
    const int b   = blockIdx.x & 15;

    // ---- stage weights: per t, 64 contiguous floats (8 heads x 8 slots) ----
    if (tid < TT * 16) {
        int tl = tid >> 4;                   // 0..15
        int f4 = tid & 15;                   // 0..15
        const float4* src = (const float4*)(g_weights + (size_t)(t0 + tl) * (B_DIM * 64) + b * 64);
        *(float4*)&ws[tl * 64 + f4 * 4] = src[f4];
    }
    // ---- stage x tile with halo, zero-padded at sequence edges ----
    for (int linear = tid; linear < XS_ROWS * (C_DIM / 4); linear += 512) {
        int irow = linear >> 7;              // 0..21
        int c4   = linear & 127;
        int tg   = t0 - 3 + irow;
        float4 v = make_float4(0.0f, 0.0f, 0.0f, 0.0f);
        if (tg >= 0 && tg < T_DIM)
            v = *(const float4*)(x + ((size_t)tg * B_DIM + b) * C_DIM + c4 * 4);
        *(float4*)&xs[irow * C_DIM + c4 * 4] = v;
    }
    __syncthreads();

    const int c  = tid;
    const int h  = c >> 6;                   // uniform per warp
    const int fb = h * 448 + (c & 63) * 7;   // flat offset of first tap

    #pragma unroll 2
    for (int tl = 0; tl < TT; tl++) {
        const float4* wp = (const float4*)&ws[tl * 64 + h * 8];   // broadcast
        float4 w0 = wp[0];
        float4 w1 = wp[1];
        const float* xp = &xs[tl * C_DIM + fb];   // 7 consecutive floats
        float acc;
        acc = w0.x * xp[0];
        acc = fmaf(w0.y, xp[1], acc);
        acc = fmaf(w0.z, xp[2], acc);
        acc = fmaf(w0.w, xp[3], acc);
        acc = fmaf(w1.x, xp[4], acc);
        acc = fmaf(w1.y, xp[5], acc);
        acc = fmaf(w1.z, xp[6], acc);
        out[((size_t)(t0 + tl) * B_DIM + b) * C_DIM + c] = acc;
    }
}

// ---------------------------------------------------------------------------
extern "C" void kernel_launch(void* const* d_in, const int* in_sizes, int n_in,
                              void* d_out, int out_size) {
    const float* x     = (const float*)d_in[0];
    const float* query = (const float*)d_in[1];
    const float* W     = (const float*)d_in[2];
    float* out         = (float*)d_out;

    cudaFuncSetAttribute(conv_kernel, cudaFuncAttributeMaxDynamicSharedMemorySize, SMEM_CONV);

    // phase 1: 32768 rows / 128 = 256 blocks x 128 threads
    gemm_softmax_kernel<<<256, 128>>>(query, W);
    // phase 2: 128 t-tiles x 16 batches
    conv_kernel<<<(T_DIM / TT) * B_DIM, 512, SMEM_CONV>>>(x, out);
}

// round 5
// speedup vs baseline: 1.1588x; 1.1588x over previous
#include <cuda_runtime.h>
#include <cstdint>

// ============================================================================
// DynamicConv1D: T=2048, B=16, C=512, H=8, R=64, K=7
//   phase 1: logits = query @ W  (32768 x 512) * (512 x 56), softmax over K=7
//   phase 2: out[t,b,h*64+r] = sum_kk w[n,h,kk] * xs[tl*512 + h*448 + r*7 + kk]
// ============================================================================

#define T_DIM 2048
#define B_DIM 16
#define C_DIM 512
#define H_DIM 8
#define K_DIM 7

// scratch: softmaxed weights, padded: [row(=t*16+b)] [8 heads] [8 slots]
__device__ float g_weights[(size_t)T_DIM * B_DIM * H_DIM * 8];

// ---------------------------------------------------------------------------
// Kernel 1: GEMM (M=32768, N=56, K=512) + fused softmax.
// BM=64 -> 512 blocks (3.46/SM). 256 threads = 8 warps, warp w == head w.
// Lane owns rows {2*lane, 2*lane+1} -> ONE f32x2 accumulator pack x 7 cols.
// A tile K-major, stride BMP=66 (even: keeps LDS.64 8B-aligned; stores <=2-way).
// B tile lane-duplicated float2 [kk][head*8+j]; reads are warp-uniform
// broadcasts (1 wf each). Per warp-kk: 1 LDS.64 + 4 LDS.128 + 7 FFMA2.
// ---------------------------------------------------------------------------
#define BM  64
#define BK  32
#define BMP 66

__device__ __forceinline__ unsigned long long fma2(unsigned long long a,
                                                   unsigned long long b,
                                                   unsigned long long c) {
    asm("fma.rn.f32x2 %0, %1, %2, %0;" : "+l"(c) : "l"(a), "l"(b));
    return c;
}

__global__ __launch_bounds__(256, 4)
void gemm_softmax_kernel(const float* __restrict__ query,
                         const float* __restrict__ W) {
    __shared__ float  As[BK * BMP];     // [kk][row], 8448 B
    __shared__ float2 Bsd[BK * 64];     // [kk][head*8+j] duplicated, 16384 B

    const int tid      = threadIdx.x;
    const int lane     = tid & 31;
    const int head     = tid >> 5;                // warp id == head
    const int blockRow = blockIdx.x * BM;

    unsigned long long acc[7];
    #pragma unroll
    for (int j = 0; j < 7; j++) acc[j] = 0ULL;

    for (int k0 = 0; k0 < C_DIM; k0 += BK) {
        // ---- load A tile (64 rows x 32 kk), store K-major: 512 float4 ----
        #pragma unroll
        for (int l = 0; l < 2; l++) {
            int linear = tid + l * 256;        // 0..511
            int row    = linear >> 3;          // 0..63
            int f4     = linear & 7;           // 0..7 (kk quad)
            float4 v = *(const float4*)(query + (size_t)(blockRow + row) * C_DIM + k0 + f4 * 4);
            As[(f4 * 4 + 0) * BMP + row] = v.x;
            As[(f4 * 4 + 1) * BMP + row] = v.y;
            As[(f4 * 4 + 2) * BMP + row] = v.z;
            As[(f4 * 4 + 3) * BMP + row] = v.w;
        }
        // ---- load B tile, lane-duplicated float2: 2048 slots, 8/thread ----
        #pragma unroll
        for (int l = 0; l < 8; l++) {
            int linear = tid + l * 256;        // 0..2047
            int kk   = linear >> 6;
            int slot = linear & 63;
            int hs   = slot >> 3;
            int jj   = slot & 7;
            float w = 0.0f;
            if (jj < 7) w = W[(k0 + kk) * 56 + hs * 7 + jj];
            Bsd[linear] = make_float2(w, w);
        }
        __syncthreads();

        #pragma unroll
        for (int kk = 0; kk < BK; kk++) {
            // A: rows {2*lane, 2*lane+1} -> one aligned LDS.64 (f32x2 pack)
            unsigned long long a = *(const unsigned long long*)&As[kk * BMP + 2 * lane];
            // B: 7 duplicated pairs for this head (warp-uniform broadcast)
            const ulonglong2* bp = (const ulonglong2*)&Bsd[kk * 64 + head * 8];
            ulonglong2 b01 = bp[0], b23 = bp[1], b45 = bp[2], b67 = bp[3];
            unsigned long long b[7] = {b01.x, b01.y, b23.x, b23.y, b45.x, b45.y, b67.x};
            #pragma unroll
            for (int j = 0; j < 7; j++)
                acc[j] = fma2(a, b[j], acc[j]);
        }
        __syncthreads();
    }

    // ---- unpack, softmax over the 7 taps, store padded to 8 ----
    {
        float lo[7], hi[7];
        #pragma unroll
        for (int j = 0; j < 7; j++) {
            unsigned int ulo, uhi;
            asm("mov.b64 {%0, %1}, %2;" : "=r"(ulo), "=r"(uhi) : "l"(acc[j]));
            lo[j] = __uint_as_float(ulo);
            hi[j] = __uint_as_float(uhi);
        }
        #pragma unroll
        for (int half = 0; half < 2; half++) {
            float* v = half ? hi : lo;
            int rowGlobal = blockRow + 2 * lane + half;
            float m = v[0];
            #pragma unroll
            for (int j = 1; j < 7; j++) m = fmaxf(m, v[j]);
            float e[7], s = 0.0f;
            #pragma unroll
            for (int j = 0; j < 7; j++) { e[j] = __expf(v[j] - m); s += e[j]; }
            float inv = 1.0f / s;
            size_t n8 = ((size_t)rowGlobal * 8 + head) * 8;
            *(float4*)&g_weights[n8]     = make_float4(e[0]*inv, e[1]*inv, e[2]*inv, e[3]*inv);
            *(float4*)&g_weights[n8 + 4] = make_float4(e[4]*inv, e[5]*inv, e[6]*inv, 0.0f);
        }
    }
}

// ---------------------------------------------------------------------------
// Kernel 2: gathered conv (known-good R1 config: 44 us). Block = (t-tile of
// 16, one b). 512 threads, thread owns one channel c for all 16 t. x staged
// in smem [22 x 512] (halo 3+3), weights staged [16 x 64]. Taps are 7
// consecutive smem floats (lane stride 7 words -> conflict-free, gcd(7,32)=1).
// smem = 48 KB -> 3 blocks/SM, no reg cap (40 regs).
// ---------------------------------------------------------------------------
#define TT 16
#define XS_ROWS (TT + K_DIM - 1)            // 22
#define SMEM_CONV ((XS_ROWS * C_DIM + TT * 64) * 4)   // 49152 bytes

__global__ __launch_bounds__(512, 3)
void conv_kernel(const float* __restrict__ x, float* __restrict__ out) {
    extern __shared__ float smem[];
    float* xs = smem;                        // 22*512
    float* ws = smem + XS_ROWS * C_DIM;      // 16*64

    const int tid = threadIdx.x;
    const int t0  = (blockIdx.x >> 4) * TT;
    const int b   = blockIdx.x & 15;

    // ---- stage weights: per t, 64 contiguous floats (8 heads x 8 slots) ----
    if (tid < TT * 16) {
        int tl = tid >> 4;                   // 0..15
        int f4 = tid & 15;                   // 0..15
        const float4* src = (const float4*)(g_weights + (size_t)(t0 + tl) * (B_DIM * 64) + b * 64);
        *(float4*)&ws[tl * 64 + f4 * 4] = src[f4];
    }
    // ---- stage x tile with halo, zero-padded at sequence edges ----
    for (int linear = tid; linear < XS_ROWS * (C_DIM / 4); linear += 512) {
        int irow = linear >> 7;              // 0..21
        int c4   = linear & 127;
        int tg   = t0 - 3 + irow;
        float4 v = make_float4(0.0f, 0.0f, 0.0f, 0.0f);
        if (tg >= 0 && tg < T_DIM)
            v = *(const float4*)(x + ((size_t)tg * B_DIM + b) * C_DIM + c4 * 4);
        *(float4*)&xs[irow * C_DIM + c4 * 4] = v;
    }
    __syncthreads();

    const int c  = tid;
    const int h  = c >> 6;                   // uniform per warp
    const int fb = h * 448 + (c & 63) * 7;   // flat offset of first tap

    #pragma unroll 4
    for (int tl = 0; tl < TT; tl++) {
        const float4* wp = (const float4*)&ws[tl * 64 + h * 8];   // broadcast
        float4 w0 = wp[0];
        float4 w1 = wp[1];
        const float* xp = &xs[tl * C_DIM + fb];   // 7 consecutive floats
        float acc;
        acc = w0.x * xp[0];
        acc = fmaf(w0.y, xp[1], acc);
        acc = fmaf(w0.z, xp[2], acc);
        acc = fmaf(w0.w, xp[3], acc);
        acc = fmaf(w1.x, xp[4], acc);
        acc = fmaf(w1.y, xp[5], acc);
        acc = fmaf(w1.z, xp[6], acc);
        out[((size_t)(t0 + tl) * B_DIM + b) * C_DIM + c] = acc;
    }
}

// ---------------------------------------------------------------------------
extern "C" void kernel_launch(void* const* d_in, const int* in_sizes, int n_in,
                              void* d_out, int out_size) {
    const float* x     = (const float*)d_in[0];
    const float* query = (const float*)d_in[1];
    const float* W     = (const float*)d_in[2];
    float* out         = (float*)d_out;

    cudaFuncSetAttribute(conv_kernel, cudaFuncAttributeMaxDynamicSharedMemorySize, SMEM_CONV);

    // phase 1: 32768 rows / 64 = 512 blocks x 256 threads
    gemm_softmax_kernel<<<512, 256>>>(query, W);
    // phase 2: 128 t-tiles x 16 batches
    conv_kernel<<<(T_DIM / TT) * B_DIM, 512, SMEM_CONV>>>(x, out);
}